// round 16
// baseline (speedup 1.0000x reference)
#include <cuda_runtime.h>
#include <cuda_fp16.h>
#include <cstdint>

#define B_   4
#define S_   2048
#define D_   1024
#define H_   16
#define HD_  64
#define NTOK (B_ * S_)   // 8192

// Scratch (device globals: allocation-free per harness rules)
static __device__ __align__(16) __half g_Q16[NTOK * D_];   // projected Q (x0.125), fp16
static __device__ __align__(16) __half g_K16[NTOK * D_];
static __device__ __align__(16) __half g_V16[NTOK * D_];
static __device__ __align__(16) __half g_O16[NTOK * D_];   // attention output, fp16
static __device__ __align__(16) __half g_W16[4][D_ * D_];  // converted weights

// ===========================================================================
// PTX helpers (sm_100-safe: cp.async + fp16 mma.sync + ldmatrix)
// ===========================================================================
__device__ __forceinline__ void cp_async16(uint32_t dst, const void* src) {
    asm volatile("cp.async.cg.shared.global [%0], [%1], 16;\n"
                 :: "r"(dst), "l"(src));
}
#define CP_COMMIT() asm volatile("cp.async.commit_group;\n" ::: "memory")
#define CP_WAIT(n)  asm volatile("cp.async.wait_group %0;\n" :: "n"(n) : "memory")

__device__ __forceinline__ uint32_t smem_u32(const void* p) {
    uint32_t a;
    asm("{ .reg .u64 t; cvta.to.shared.u64 t, %1; cvt.u32.u64 %0, t; }"
        : "=r"(a) : "l"(p));
    return a;
}
__device__ __forceinline__ void ldsm4(uint32_t& r0, uint32_t& r1, uint32_t& r2,
                                      uint32_t& r3, uint32_t a) {
    asm volatile("ldmatrix.sync.aligned.m8n8.x4.shared.b16 {%0,%1,%2,%3}, [%4];"
                 : "=r"(r0), "=r"(r1), "=r"(r2), "=r"(r3) : "r"(a));
}
__device__ __forceinline__ void ldsm4t(uint32_t& r0, uint32_t& r1, uint32_t& r2,
                                       uint32_t& r3, uint32_t a) {
    asm volatile("ldmatrix.sync.aligned.m8n8.x4.trans.shared.b16 {%0,%1,%2,%3}, [%4];"
                 : "=r"(r0), "=r"(r1), "=r"(r2), "=r"(r3) : "r"(a));
}
__device__ __forceinline__ void mma16(float* d, const uint32_t* a, const uint32_t* b) {
    asm volatile(
        "mma.sync.aligned.m16n8k16.row.col.f32.f16.f16.f32 "
        "{%0,%1,%2,%3}, {%4,%5,%6,%7}, {%8,%9}, {%0,%1,%2,%3};"
        : "+f"(d[0]), "+f"(d[1]), "+f"(d[2]), "+f"(d[3])
        : "r"(a[0]), "r"(a[1]), "r"(a[2]), "r"(a[3]), "r"(b[0]), "r"(b[1]));
}
__device__ __forceinline__ uint32_t pack_h2(float lo, float hi) {
    __half2 h = __floats2half2_rn(lo, hi);     // cvt.rn.f16x2.f32 (single SASS)
    return *reinterpret_cast<uint32_t*>(&h);
}

// ===========================================================================
// fp32 -> fp16 conversion: WEIGHTS ONLY (activations fused into qkv GEMM)
// ===========================================================================
__global__ __launch_bounds__(256) void cvt_kernel(
    const float* __restrict__ Wq, const float* __restrict__ Wk,
    const float* __restrict__ Wv, const float* __restrict__ Wo)
{
    const float* ws[4] = { Wq, Wk, Wv, Wo };
    const float4* s4 = (const float4*)ws[blockIdx.y];
    uint4* d4 = (uint4*)g_W16[blockIdx.y];
    const uint32_t n8 = D_ * D_ / 8;
    for (uint32_t i = blockIdx.x * 256 + threadIdx.x; i < n8; i += gridDim.x * 256) {
        float4 a = s4[2 * i];
        float4 b = s4[2 * i + 1];
        uint4 o;
        o.x = pack_h2(a.x, a.y);
        o.y = pack_h2(a.z, a.w);
        o.z = pack_h2(b.x, b.y);
        o.w = pack_h2(b.z, b.w);
        d4[i] = o;
    }
}

// ===========================================================================
// Shared tiling constants
// ===========================================================================
#define BKH  64
#define LDH  72                        // halves row stride (B operand / fp16 A)
#define LDA32 72                       // float row stride (fp32 A operand)
#define NCH  (D_ / BKH)                // 16

// ---- qkv GEMM (fp32 A fused conversion, 2-stage) ----
#define ASTG32 (128 * LDA32 * 4)       // 36864 B fp32 A per stage
#define BSTG16 (128 * LDH * 2)         // 18432 B fp16 B per stage
#define QSTGB  (ASTG32 + BSTG16)       // 55296 B per stage
#define QGSMEM (2 * QSTGB)             // 110592 -> 2 CTAs/SM

// ---- out GEMM (fp16 A, 3-stage; round-12 proven) ----
#define STGH (128 * LDH)
#define STGB16 (2 * STGH * 2)          // 36864
#define NSTG 3
#define GSMEM (NSTG * STGB16)          // 110592

// ===========================================================================
// qkv GEMM: C16 = (Afp32 @ W16^T + bias) * scale, conversion fused in A-path.
// CTA 128x128, 256 thr (8 warps 4m x 2n), 2-stage cp.async, trailing sync.
// ===========================================================================
__device__ __forceinline__ void ld_stage_qkv(const float* __restrict__ A,
                                             const __half* __restrict__ W,
                                             int bm, int bn, int kk,
                                             uint32_t sbase, int tid) {
#pragma unroll
    for (int i = 0; i < 8; ++i) {      // A fp32: 128 rows x 16 chunks (4 floats)
        int idx = i * 256 + tid;
        int r = idx >> 4, c = idx & 15;
        cp_async16(sbase + (r * LDA32 + c * 4) * 4,
                   A + (size_t)(bm + r) * D_ + kk + c * 4);
    }
#pragma unroll
    for (int i = 0; i < 4; ++i) {      // B fp16: 128 rows x 8 chunks (8 halves)
        int idx = i * 256 + tid;
        int r = idx >> 3, c = idx & 7;
        cp_async16(sbase + ASTG32 + (r * LDH + c * 8) * 2,
                   W + (size_t)(bn + r) * D_ + kk + c * 8);
    }
}

__device__ void gemm_qkv_body(const float* __restrict__ A, const __half* __restrict__ W,
                              const float* __restrict__ bias, __half* __restrict__ C,
                              float scale) {
    extern __shared__ __half shq[];
    const uint32_t sb_u = smem_u32(shq);
    float* smA = (float*)shq;

    const int tid = threadIdx.x, lane = tid & 31, warp = tid >> 5;
    const int wm = warp & 3, wn = warp >> 2;           // 4 x 2 warp grid
    const int g = lane >> 2, tg = lane & 3;
    const int bm = blockIdx.y * 128, bn = blockIdx.x * 128;

    // B ldmatrix lane geometry
    const int bRow = wn * 64 + (lane & 7) + ((lane >> 4) & 1) * 8;  // + p*16
    const int bK   = ((lane >> 3) & 1) * 8;
    // A fragment rows for this thread
    const int ar0 = wm * 32 + g;                       // + mi*16 (+8 for upper)

    float d[2][8][4];
#pragma unroll
    for (int mi = 0; mi < 2; ++mi)
#pragma unroll
        for (int ni = 0; ni < 8; ++ni)
#pragma unroll
            for (int r = 0; r < 4; ++r) d[mi][ni][r] = 0.f;

    ld_stage_qkv(A, W, bm, bn, 0, sb_u, tid);
    CP_COMMIT();

    for (int k = 0; k < NCH; ++k) {
        if (k + 1 < NCH) {
            ld_stage_qkv(A, W, bm, bn, (k + 1) * BKH,
                         sb_u + ((k + 1) & 1) * QSTGB, tid);
            CP_COMMIT();
            CP_WAIT(1);
        } else {
            CP_WAIT(0);
        }
        __syncthreads();

        const float* as = smA + (k & 1) * (QSTGB / 4);
        const uint32_t sB = sb_u + (k & 1) * QSTGB + ASTG32;
#pragma unroll
        for (int kk = 0; kk < BKH; kk += 16) {
            // A fragments: fp32 LDS.64 pairs -> cvt.rn.f16x2 (rn == cvt kernel)
            uint32_t af[2][4];
#pragma unroll
            for (int mi = 0; mi < 2; ++mi) {
                const int r0 = ar0 + mi * 16;
                float2 x0 = *(const float2*)(as + r0       * LDA32 + kk + 2 * tg);
                float2 x1 = *(const float2*)(as + (r0 + 8) * LDA32 + kk + 2 * tg);
                float2 x2 = *(const float2*)(as + r0       * LDA32 + kk + 8 + 2 * tg);
                float2 x3 = *(const float2*)(as + (r0 + 8) * LDA32 + kk + 8 + 2 * tg);
                af[mi][0] = pack_h2(x0.x, x0.y);
                af[mi][1] = pack_h2(x1.x, x1.y);
                af[mi][2] = pack_h2(x2.x, x2.y);
                af[mi][3] = pack_h2(x3.x, x3.y);
            }
            uint32_t bf[8][2];
#pragma unroll
            for (int p = 0; p < 4; ++p)
                ldsm4(bf[2 * p][0], bf[2 * p][1], bf[2 * p + 1][0], bf[2 * p + 1][1],
                      sB + ((bRow + p * 16) * LDH + kk + bK) * 2);
#pragma unroll
            for (int mi = 0; mi < 2; ++mi)
#pragma unroll
                for (int ni = 0; ni < 8; ++ni)
                    mma16(d[mi][ni], af[mi], bf[ni]);
        }
        __syncthreads();   // all warps done with buf k&1 before it is reloaded
    }

#pragma unroll
    for (int mi = 0; mi < 2; ++mi) {
#pragma unroll
        for (int ni = 0; ni < 8; ++ni) {
            const int row0 = bm + wm * 32 + mi * 16 + g;
            const int col  = bn + wn * 64 + ni * 8 + 2 * tg;
            const float2 bv = *(const float2*)(bias + col);
            *(__half2*)(C + (size_t)row0 * D_ + col) =
                __floats2half2_rn((d[mi][ni][0] + bv.x) * scale,
                                  (d[mi][ni][1] + bv.y) * scale);
            *(__half2*)(C + (size_t)(row0 + 8) * D_ + col) =
                __floats2half2_rn((d[mi][ni][2] + bv.x) * scale,
                                  (d[mi][ni][3] + bv.y) * scale);
        }
    }
}

__global__ __launch_bounds__(256, 2) void qkv_gemm_kernel(
    const float* __restrict__ q, const float* __restrict__ k, const float* __restrict__ v,
    const float* __restrict__ bq, const float* __restrict__ bk,
    const float* __restrict__ bv)
{
    if (blockIdx.z == 0)      gemm_qkv_body(q, g_W16[0], bq, g_Q16, 0.125f);
    else if (blockIdx.z == 1) gemm_qkv_body(k, g_W16[1], bk, g_K16, 1.0f);
    else                      gemm_qkv_body(v, g_W16[2], bv, g_V16, 1.0f);
}

// ===========================================================================
// out GEMM: fp16 A (g_O16), round-12 proven 3-stage path. fp32 output.
// ===========================================================================
__device__ __forceinline__ void ld_stage16(const __half* __restrict__ A,
                                           const __half* __restrict__ W,
                                           int bm, int bn, int kk,
                                           uint32_t sbase, int tid) {
#pragma unroll
    for (int i = 0; i < 4; ++i) {
        int idx = i * 256 + tid;
        int r = idx >> 3, c = idx & 7;
        cp_async16(sbase + (r * LDH + c * 8) * 2,
                   A + (size_t)(bm + r) * D_ + kk + c * 8);
    }
#pragma unroll
    for (int i = 0; i < 4; ++i) {
        int idx = i * 256 + tid;
        int r = idx >> 3, c = idx & 7;
        cp_async16(sbase + STGH * 2 + (r * LDH + c * 8) * 2,
                   W + (size_t)(bn + r) * D_ + kk + c * 8);
    }
}

__global__ __launch_bounds__(256, 2) void out_gemm_kernel(
    const float* __restrict__ bo, float* __restrict__ out)
{
    extern __shared__ __half sh16[];
    const uint32_t sb_u = smem_u32(sh16);
    const __half* A = g_O16;
    const __half* W = g_W16[3];

    const int tid = threadIdx.x, lane = tid & 31, warp = tid >> 5;
    const int wm = warp & 3, wn = warp >> 2;
    const int g = lane >> 2, tg = lane & 3;
    const int bm = blockIdx.y * 128, bn = blockIdx.x * 128;

    const int aRow = wm * 32 + (lane & 7) + ((lane >> 3) & 1) * 8;
    const int aK   = ((lane >> 4) & 1) * 8;
    const int bRow = wn * 64 + (lane & 7) + ((lane >> 4) & 1) * 8;
    const int bK   = ((lane >> 3) & 1) * 8;

    float d[2][8][4];
#pragma unroll
    for (int mi = 0; mi < 2; ++mi)
#pragma unroll
        for (int ni = 0; ni < 8; ++ni)
#pragma unroll
            for (int r = 0; r < 4; ++r) d[mi][ni][r] = 0.f;

    ld_stage16(A, W, bm, bn, 0, sb_u, tid);
    CP_COMMIT();
    ld_stage16(A, W, bm, bn, BKH, sb_u + STGB16, tid);
    CP_COMMIT();

    int sidx = 0;
    for (int k = 0; k < NCH; ++k) {
        if (k + 1 < NCH) { CP_WAIT(1); }
        else             { CP_WAIT(0); }
        __syncthreads();
        if (k + 2 < NCH) {
            int ns = sidx + 2; if (ns >= NSTG) ns -= NSTG;
            ld_stage16(A, W, bm, bn, (k + 2) * BKH, sb_u + ns * STGB16, tid);
            CP_COMMIT();
        }

        const uint32_t sA = sb_u + sidx * STGB16;
        const uint32_t sB = sA + STGH * 2;
#pragma unroll
        for (int kk = 0; kk < BKH; kk += 16) {
            uint32_t af[2][4], bf[8][2];
#pragma unroll
            for (int mi = 0; mi < 2; ++mi)
                ldsm4(af[mi][0], af[mi][1], af[mi][2], af[mi][3],
                      sA + ((aRow + mi * 16) * LDH + kk + aK) * 2);
#pragma unroll
            for (int p = 0; p < 4; ++p)
                ldsm4(bf[2 * p][0], bf[2 * p][1], bf[2 * p + 1][0], bf[2 * p + 1][1],
                      sB + ((bRow + p * 16) * LDH + kk + bK) * 2);
#pragma unroll
            for (int mi = 0; mi < 2; ++mi)
#pragma unroll
                for (int ni = 0; ni < 8; ++ni)
                    mma16(d[mi][ni], af[mi], bf[ni]);
        }
        if (++sidx == NSTG) sidx = 0;
    }

#pragma unroll
    for (int mi = 0; mi < 2; ++mi) {
#pragma unroll
        for (int ni = 0; ni < 8; ++ni) {
            const int row0 = bm + wm * 32 + mi * 16 + g;
            const int col  = bn + wn * 64 + ni * 8 + 2 * tg;
            const float2 bv = *(const float2*)(bo + col);
            *(float2*)(out + (size_t)row0 * D_ + col) =
                make_float2(d[mi][ni][0] + bv.x, d[mi][ni][1] + bv.y);
            *(float2*)(out + (size_t)(row0 + 8) * D_ + col) =
                make_float2(d[mi][ni][2] + bv.x, d[mi][ni][3] + bv.y);
        }
    }
}

// ===========================================================================
// fp16 mma.sync causal flash attention (round-12 winner, unchanged).
// Q-tile 128 x 64, KV-tile 64. 8 warps; warp owns 16 full S rows.
// P entirely in registers (S D-frag layout == PV A-frag layout).
// ===========================================================================
#define QT_  128
#define KT_  64
#define KVB  (2 * KT_ * LDH * 2)                 // K+V bytes per buffer (18432)
#define PB   (QT_ * LDH * 2)                     // Q staging bytes (18432)
#define FLASH_SMEM (2 * KVB + PB)                // 55296 bytes

__device__ __forceinline__ void flash_ld_kv16(const __half* __restrict__ Kg,
                                              const __half* __restrict__ Vg,
                                              uint32_t kbuf_u, int tid) {
#pragma unroll
    for (int i = 0; i < 2; ++i) {               // K: 64 rows x 8 chunks
        int t = i * 256 + tid;
        int r = t >> 3, c = t & 7;
        cp_async16(kbuf_u + (r * LDH + c * 8) * 2, Kg + (size_t)r * D_ + c * 8);
    }
#pragma unroll
    for (int i = 0; i < 2; ++i) {               // V
        int t = i * 256 + tid;
        int r = t >> 3, c = t & 7;
        cp_async16(kbuf_u + KT_ * LDH * 2 + (r * LDH + c * 8) * 2,
                   Vg + (size_t)r * D_ + c * 8);
    }
}

__global__ __launch_bounds__(256, 2) void flash_kernel()
{
    extern __shared__ __half fsh16[];
    const uint32_t fsh_u = smem_u32(fsh16);
    const uint32_t Ps_u = fsh_u + 2 * KVB;      // Q staging region
    __half* Ps = fsh16 + 2 * (KVB / 2);

    const int tid = threadIdx.x, lane = tid & 31, warp = tid >> 5;
    const int g = lane >> 2, tg = lane & 3;
    const int qt = (gridDim.x - 1) - blockIdx.x;       // heavy blocks first
    const int h  = blockIdx.y;
    const int b  = blockIdx.z;
    const size_t base = (size_t)b * S_ * D_ + h * HD_;
    const int m0 = warp * 16;

    // ldmatrix lane geometry
    const int aRowL = m0 + (lane & 7) + ((lane >> 3) & 1) * 8;
    const int aKL   = ((lane >> 4) & 1) * 8;
    const int bRowL = (lane & 7) + ((lane >> 4) & 1) * 8;
    const int bKL   = ((lane >> 3) & 1) * 8;
    const int vRowL = (lane & 7) + ((lane >> 3) & 1) * 8;
    const int vColL = ((lane >> 4) & 1) * 8;

    // ---- Stage Q via smem once, hoist fragments to registers ----
    uint32_t aq[4][4];
    {
        const uint4* Qg = (const uint4*)(g_Q16 + base + (size_t)qt * QT_ * D_);
        for (int t = tid; t < QT_ * 8; t += 256) {
            int r = t >> 3, c = t & 7;
            *(uint4*)(Ps + r * LDH + c * 8) = Qg[(size_t)r * (D_ / 8) + c];
        }
        __syncthreads();
#pragma unroll
        for (int ki = 0; ki < 4; ++ki)
            ldsm4(aq[ki][0], aq[ki][1], aq[ki][2], aq[ki][3],
                  Ps_u + (aRowL * LDH + ki * 16 + aKL) * 2);
    }

    float m0r = -1e30f, m1r = -1e30f, l0 = 0.f, l1 = 0.f;
    float d_o[8][4];
#pragma unroll
    for (int ni = 0; ni < 8; ++ni)
#pragma unroll
        for (int r = 0; r < 4; ++r) d_o[ni][r] = 0.f;

    const int njt = 2 * qt + 2;

    flash_ld_kv16(g_K16 + base, g_V16 + base, fsh_u, tid);
    CP_COMMIT();

    for (int jt = 0; jt < njt; ++jt) {
        CP_WAIT(0);
        __syncthreads();
        if (jt + 1 < njt) {
            flash_ld_kv16(g_K16 + base + (size_t)(jt + 1) * KT_ * D_,
                          g_V16 + base + (size_t)(jt + 1) * KT_ * D_,
                          fsh_u + ((jt + 1) & 1) * KVB, tid);
            CP_COMMIT();
        }

        const uint32_t Ks_u = fsh_u + (jt & 1) * KVB;
        const uint32_t Vs_u = Ks_u + KT_ * LDH * 2;

        // ---- S = Q @ K^T ----
        float ds[8][4];
#pragma unroll
        for (int ni = 0; ni < 8; ++ni)
#pragma unroll
            for (int r = 0; r < 4; ++r) ds[ni][r] = 0.f;

#pragma unroll
        for (int ki = 0; ki < 4; ++ki) {
            const int kk = ki * 16;
            uint32_t bf[8][2];
#pragma unroll
            for (int p = 0; p < 4; ++p)
                ldsm4(bf[2 * p][0], bf[2 * p][1], bf[2 * p + 1][0], bf[2 * p + 1][1],
                      Ks_u + ((bRowL + p * 16) * LDH + kk + bKL) * 2);
#pragma unroll
            for (int ni = 0; ni < 8; ++ni)
                mma16(ds[ni], aq[ki], bf[ni]);
        }

        // ---- causal mask (diagonal-region KV tiles only) ----
        if (jt >= 2 * qt) {
            const int grow0 = qt * QT_ + m0 + g;
            const int grow1 = grow0 + 8;
#pragma unroll
            for (int ni = 0; ni < 8; ++ni) {
                const int c0 = jt * KT_ + ni * 8 + 2 * tg;
                if (c0     > grow0) ds[ni][0] = -1e30f;
                if (c0 + 1 > grow0) ds[ni][1] = -1e30f;
                if (c0     > grow1) ds[ni][2] = -1e30f;
                if (c0 + 1 > grow1) ds[ni][3] = -1e30f;
            }
        }

        // ---- online softmax (rows fully in-warp) ----
        float rm0 = -1e30f, rm1 = -1e30f;
#pragma unroll
        for (int ni = 0; ni < 8; ++ni) {
            rm0 = fmaxf(rm0, fmaxf(ds[ni][0], ds[ni][1]));
            rm1 = fmaxf(rm1, fmaxf(ds[ni][2], ds[ni][3]));
        }
        rm0 = fmaxf(rm0, __shfl_xor_sync(0xffffffffu, rm0, 1));
        rm0 = fmaxf(rm0, __shfl_xor_sync(0xffffffffu, rm0, 2));
        rm1 = fmaxf(rm1, __shfl_xor_sync(0xffffffffu, rm1, 1));
        rm1 = fmaxf(rm1, __shfl_xor_sync(0xffffffffu, rm1, 2));

        const float mn0 = fmaxf(m0r, rm0);
        const float mn1 = fmaxf(m1r, rm1);
        const float a0 = __expf(m0r - mn0);
        const float a1 = __expf(m1r - mn1);
        m0r = mn0; m1r = mn1;

        // ---- exp + pack P directly into A-fragment registers ----
        uint32_t pp[8][2];
        float rs0 = 0.f, rs1 = 0.f;
#pragma unroll
        for (int ni = 0; ni < 8; ++ni) {
            float p00 = __expf(ds[ni][0] - mn0);
            float p01 = __expf(ds[ni][1] - mn0);
            float p10 = __expf(ds[ni][2] - mn1);
            float p11 = __expf(ds[ni][3] - mn1);
            rs0 += p00 + p01;
            rs1 += p10 + p11;
            pp[ni][0] = pack_h2(p00, p01);   // rows g   (vals 0,1)
            pp[ni][1] = pack_h2(p10, p11);   // rows g+8 (vals 2,3)
        }
        rs0 += __shfl_xor_sync(0xffffffffu, rs0, 1);
        rs0 += __shfl_xor_sync(0xffffffffu, rs0, 2);
        rs1 += __shfl_xor_sync(0xffffffffu, rs1, 1);
        rs1 += __shfl_xor_sync(0xffffffffu, rs1, 2);
        l0 = l0 * a0 + rs0;
        l1 = l1 * a1 + rs1;

#pragma unroll
        for (int ni = 0; ni < 8; ++ni) {
            d_o[ni][0] *= a0; d_o[ni][1] *= a0;
            d_o[ni][2] *= a1; d_o[ni][3] *= a1;
        }

        // ---- O += P @ V  (A-frag = pp registers; B = V^T via ldmatrix.trans)
#pragma unroll
        for (int ki = 0; ki < 4; ++ki) {
            const int kk = ki * 16;
            uint32_t ap[4] = { pp[2 * ki][0], pp[2 * ki][1],
                               pp[2 * ki + 1][0], pp[2 * ki + 1][1] };
            uint32_t bv[8][2];
#pragma unroll
            for (int p = 0; p < 4; ++p)
                ldsm4t(bv[2 * p][0], bv[2 * p][1], bv[2 * p + 1][0], bv[2 * p + 1][1],
                       Vs_u + ((kk + vRowL) * LDH + p * 16 + vColL) * 2);
#pragma unroll
            for (int ni = 0; ni < 8; ++ni)
                mma16(d_o[ni], ap, bv[ni]);
        }
    }

    // ---- normalize + store fp16 (input to out_gemm) ----
    const float inv0 = 1.0f / l0;
    const float inv1 = 1.0f / l1;
    __half* Og = g_O16 + base + (size_t)qt * QT_ * D_;
    const int row0 = m0 + g;
#pragma unroll
    for (int ni = 0; ni < 8; ++ni) {
        const int col = ni * 8 + 2 * tg;
        *(__half2*)(Og + (size_t)row0 * D_ + col) =
            __floats2half2_rn(d_o[ni][0] * inv0, d_o[ni][1] * inv0);
        *(__half2*)(Og + (size_t)(row0 + 8) * D_ + col) =
            __floats2half2_rn(d_o[ni][2] * inv1, d_o[ni][3] * inv1);
    }
}

// ---------------------------------------------------------------------------
extern "C" void kernel_launch(void* const* d_in, const int* in_sizes, int n_in,
                              void* d_out, int out_size)
{
    const float* q  = (const float*)d_in[0];
    const float* k  = (const float*)d_in[1];
    const float* v  = (const float*)d_in[2];
    // d_in[3]: mask — fixed causal tril, handled analytically in flash_kernel
    const float* Wq = (const float*)d_in[4];
    const float* bq = (const float*)d_in[5];
    const float* Wk = (const float*)d_in[6];
    const float* bk = (const float*)d_in[7];
    const float* Wv = (const float*)d_in[8];
    const float* bv = (const float*)d_in[9];
    const float* Wo = (const float*)d_in[10];
    const float* bo = (const float*)d_in[11];
    float* out = (float*)d_out;

    static bool s_configured = false;
    if (!s_configured) {
        cudaFuncSetAttribute(flash_kernel,
                             cudaFuncAttributeMaxDynamicSharedMemorySize, FLASH_SMEM);
        cudaFuncSetAttribute(qkv_gemm_kernel,
                             cudaFuncAttributeMaxDynamicSharedMemorySize, QGSMEM);
        cudaFuncSetAttribute(out_gemm_kernel,
                             cudaFuncAttributeMaxDynamicSharedMemorySize, GSMEM);
        s_configured = true;
    }

    cvt_kernel<<<dim3(128, 4), 256>>>(Wq, Wk, Wv, Wo);
    qkv_gemm_kernel<<<dim3(D_ / 128, NTOK / 128, 3), 256, QGSMEM>>>(
        q, k, v, bq, bk, bv);
    flash_kernel<<<dim3(S_ / QT_, H_, B_), 256, FLASH_SMEM>>>();
    out_gemm_kernel<<<dim3(D_ / 128, NTOK / 128, 1), 256, GSMEM>>>(bo, out);
}

// round 17
// speedup vs baseline: 1.0239x; 1.0239x over previous
#include <cuda_runtime.h>
#include <cuda_fp16.h>
#include <cstdint>

#define B_   4
#define S_   2048
#define D_   1024
#define H_   16
#define HD_  64
#define NTOK (B_ * S_)   // 8192

// Scratch (device globals: allocation-free per harness rules)
static __device__ __align__(16) __half g_Q16[NTOK * D_];   // projected Q (x0.125), fp16
static __device__ __align__(16) __half g_K16[NTOK * D_];
static __device__ __align__(16) __half g_V16[NTOK * D_];
static __device__ __align__(16) __half g_O16[NTOK * D_];   // attention output, fp16
static __device__ __align__(16) __half g_q16[NTOK * D_];   // converted inputs
static __device__ __align__(16) __half g_k16[NTOK * D_];
static __device__ __align__(16) __half g_v16[NTOK * D_];
static __device__ __align__(16) __half g_W16[4][D_ * D_];  // converted weights

// ===========================================================================
// PTX helpers (sm_100-safe: cp.async + fp16 mma.sync + ldmatrix)
// ===========================================================================
__device__ __forceinline__ void cp_async16(uint32_t dst, const void* src) {
    asm volatile("cp.async.cg.shared.global [%0], [%1], 16;\n"
                 :: "r"(dst), "l"(src));
}
#define CP_COMMIT() asm volatile("cp.async.commit_group;\n" ::: "memory")
#define CP_WAIT(n)  asm volatile("cp.async.wait_group %0;\n" :: "n"(n) : "memory")

__device__ __forceinline__ uint32_t smem_u32(const void* p) {
    uint32_t a;
    asm("{ .reg .u64 t; cvta.to.shared.u64 t, %1; cvt.u32.u64 %0, t; }"
        : "=r"(a) : "l"(p));
    return a;
}
__device__ __forceinline__ void ldsm4(uint32_t& r0, uint32_t& r1, uint32_t& r2,
                                      uint32_t& r3, uint32_t a) {
    asm volatile("ldmatrix.sync.aligned.m8n8.x4.shared.b16 {%0,%1,%2,%3}, [%4];"
                 : "=r"(r0), "=r"(r1), "=r"(r2), "=r"(r3) : "r"(a));
}
__device__ __forceinline__ void ldsm4t(uint32_t& r0, uint32_t& r1, uint32_t& r2,
                                       uint32_t& r3, uint32_t a) {
    asm volatile("ldmatrix.sync.aligned.m8n8.x4.trans.shared.b16 {%0,%1,%2,%3}, [%4];"
                 : "=r"(r0), "=r"(r1), "=r"(r2), "=r"(r3) : "r"(a));
}
__device__ __forceinline__ void mma16(float* d, const uint32_t* a, const uint32_t* b) {
    asm volatile(
        "mma.sync.aligned.m16n8k16.row.col.f32.f16.f16.f32 "
        "{%0,%1,%2,%3}, {%4,%5,%6,%7}, {%8,%9}, {%0,%1,%2,%3};"
        : "+f"(d[0]), "+f"(d[1]), "+f"(d[2]), "+f"(d[3])
        : "r"(a[0]), "r"(a[1]), "r"(a[2]), "r"(a[3]), "r"(b[0]), "r"(b[1]));
}
__device__ __forceinline__ uint32_t pack_h2(float lo, float hi) {
    __half2 h = __floats2half2_rn(lo, hi);
    return *reinterpret_cast<uint32_t*>(&h);
}

// ===========================================================================
// fp32 -> fp16 conversion: 4 weight matrices + 3 activation tensors.
// One launch (grid.y = job), 16-byte stores.
// ===========================================================================
__global__ __launch_bounds__(256) void cvt_kernel(
    const float* __restrict__ q, const float* __restrict__ k, const float* __restrict__ v,
    const float* __restrict__ Wq, const float* __restrict__ Wk,
    const float* __restrict__ Wv, const float* __restrict__ Wo)
{
    const int job = blockIdx.y;
    const float* src;
    __half* dst;
    uint32_t n8;
    if (job < 4) {
        const float* ws[4] = { Wq, Wk, Wv, Wo };
        src = ws[job]; dst = g_W16[job]; n8 = D_ * D_ / 8;
    } else {
        const float* as[3] = { q, k, v };
        __half* ds[3] = { g_q16, g_k16, g_v16 };
        src = as[job - 4]; dst = ds[job - 4]; n8 = NTOK * D_ / 8;
    }
    const float4* s4 = (const float4*)src;
    uint4* d4 = (uint4*)dst;
    for (uint32_t i = blockIdx.x * 256 + threadIdx.x; i < n8; i += gridDim.x * 256) {
        float4 a = s4[2 * i];
        float4 b = s4[2 * i + 1];
        uint4 o;
        o.x = pack_h2(a.x, a.y);
        o.y = pack_h2(a.z, a.w);
        o.z = pack_h2(b.x, b.y);
        o.w = pack_h2(b.z, b.w);
        d4[i] = o;
    }
}

// ===========================================================================
// fp16 mma.sync NT GEMM (round-12/15 proven): C = (A @ W^T + bias) * scale
// CTA 128x128, BK=64 halves, 3-stage cp.async, 256 thr (8 warps 4m x 2n).
// ===========================================================================
#define BKH  64
#define LDH  72
#define STGH (128 * LDH)               // halves per operand per stage (9216)
#define STGB16 (2 * STGH * 2)          // bytes per stage (A+B) = 36864
#define NSTG 3
#define GSMEM (NSTG * STGB16)          // 110592 bytes
#define NCH  (D_ / BKH)                // 16

__device__ __forceinline__ void ld_stage16(const __half* __restrict__ A,
                                           const __half* __restrict__ W,
                                           int bm, int bn, int kk,
                                           uint32_t sbase, int tid) {
#pragma unroll
    for (int i = 0; i < 4; ++i) {      // A: 128 rows x 8 chunks(8 halves)
        int idx = i * 256 + tid;
        int r = idx >> 3, c = idx & 7;
        cp_async16(sbase + (r * LDH + c * 8) * 2,
                   A + (size_t)(bm + r) * D_ + kk + c * 8);
    }
#pragma unroll
    for (int i = 0; i < 4; ++i) {      // B(W): 128 rows x 8 chunks
        int idx = i * 256 + tid;
        int r = idx >> 3, c = idx & 7;
        cp_async16(sbase + STGH * 2 + (r * LDH + c * 8) * 2,
                   W + (size_t)(bn + r) * D_ + kk + c * 8);
    }
}

template<bool OUT_HALF>
__device__ void gemm16_body(const __half* __restrict__ A, const __half* __restrict__ W,
                            const float* __restrict__ bias, void* __restrict__ Cv,
                            float scale) {
    extern __shared__ __half sh16[];
    const uint32_t sb_u = smem_u32(sh16);

    const int tid = threadIdx.x, lane = tid & 31, warp = tid >> 5;
    const int wm = warp & 3, wn = warp >> 2;           // 4 x 2 warp grid
    const int g = lane >> 2, tg = lane & 3;
    const int bm = blockIdx.y * 128, bn = blockIdx.x * 128;

    // ldmatrix lane geometry
    const int aRow = wm * 32 + (lane & 7) + ((lane >> 3) & 1) * 8;  // + mi*16
    const int aK   = ((lane >> 4) & 1) * 8;
    const int bRow = wn * 64 + (lane & 7) + ((lane >> 4) & 1) * 8;  // + p*16
    const int bK   = ((lane >> 3) & 1) * 8;

    float d[2][8][4];
#pragma unroll
    for (int mi = 0; mi < 2; ++mi)
#pragma unroll
        for (int ni = 0; ni < 8; ++ni)
#pragma unroll
            for (int r = 0; r < 4; ++r) d[mi][ni][r] = 0.f;

    ld_stage16(A, W, bm, bn, 0, sb_u, tid);
    CP_COMMIT();
    ld_stage16(A, W, bm, bn, BKH, sb_u + STGB16, tid);
    CP_COMMIT();

    int sidx = 0;
    for (int k = 0; k < NCH; ++k) {
        if (k + 1 < NCH) { CP_WAIT(1); }
        else             { CP_WAIT(0); }
        __syncthreads();
        if (k + 2 < NCH) {
            int ns = sidx + 2; if (ns >= NSTG) ns -= NSTG;
            ld_stage16(A, W, bm, bn, (k + 2) * BKH, sb_u + ns * STGB16, tid);
            CP_COMMIT();
        }

        const uint32_t sA = sb_u + sidx * STGB16;
        const uint32_t sB = sA + STGH * 2;
#pragma unroll
        for (int kk = 0; kk < BKH; kk += 16) {
            uint32_t af[2][4], bf[8][2];
#pragma unroll
            for (int mi = 0; mi < 2; ++mi)
                ldsm4(af[mi][0], af[mi][1], af[mi][2], af[mi][3],
                      sA + ((aRow + mi * 16) * LDH + kk + aK) * 2);
#pragma unroll
            for (int p = 0; p < 4; ++p)
                ldsm4(bf[2 * p][0], bf[2 * p][1], bf[2 * p + 1][0], bf[2 * p + 1][1],
                      sB + ((bRow + p * 16) * LDH + kk + bK) * 2);
#pragma unroll
            for (int mi = 0; mi < 2; ++mi)
#pragma unroll
                for (int ni = 0; ni < 8; ++ni)
                    mma16(d[mi][ni], af[mi], bf[ni]);
        }
        if (++sidx == NSTG) sidx = 0;
    }

#pragma unroll
    for (int mi = 0; mi < 2; ++mi) {
#pragma unroll
        for (int ni = 0; ni < 8; ++ni) {
            const int row0 = bm + wm * 32 + mi * 16 + g;
            const int col  = bn + wn * 64 + ni * 8 + 2 * tg;
            const float2 bv = *(const float2*)(bias + col);
            float o00 = (d[mi][ni][0] + bv.x) * scale;
            float o01 = (d[mi][ni][1] + bv.y) * scale;
            float o10 = (d[mi][ni][2] + bv.x) * scale;
            float o11 = (d[mi][ni][3] + bv.y) * scale;
            if (OUT_HALF) {
                __half* C = (__half*)Cv;
                *(__half2*)(C + (size_t)row0 * D_ + col)       = __floats2half2_rn(o00, o01);
                *(__half2*)(C + (size_t)(row0 + 8) * D_ + col) = __floats2half2_rn(o10, o11);
            } else {
                float* C = (float*)Cv;
                *(float2*)(C + (size_t)row0 * D_ + col)       = make_float2(o00, o01);
                *(float2*)(C + (size_t)(row0 + 8) * D_ + col) = make_float2(o10, o11);
            }
        }
    }
}

__global__ __launch_bounds__(256, 2) void qkv_gemm_kernel(
    const float* __restrict__ bq, const float* __restrict__ bk,
    const float* __restrict__ bv)
{
    if (blockIdx.z == 0)      gemm16_body<true>(g_q16, g_W16[0], bq, g_Q16, 0.125f);
    else if (blockIdx.z == 1) gemm16_body<true>(g_k16, g_W16[1], bk, g_K16, 1.0f);
    else                      gemm16_body<true>(g_v16, g_W16[2], bv, g_V16, 1.0f);
}

__global__ __launch_bounds__(256, 2) void out_gemm_kernel(
    const float* __restrict__ bo, float* __restrict__ out)
{
    gemm16_body<false>(g_O16, g_W16[3], bo, out, 1.0f);
}

// ===========================================================================
// fp16 mma.sync causal flash attention.
// Q-tile 128 x 64, KV-tile 64. 8 warps; warp owns 16 full S rows.
// P entirely in registers (S D-frag layout == PV A-frag layout).
// NEW: warps 0-3 skip the final diagonal KV tile (jt = 2qt+1) entirely —
// all their columns are masked there, and the online-softmax update for a
// fully-masked tile is an exact no-op (alpha=1, exp underflows to 0).
// ===========================================================================
#define QT_  128
#define KT_  64
#define KVB  (2 * KT_ * LDH * 2)                 // K+V bytes per buffer (18432)
#define PB   (QT_ * LDH * 2)                     // Q staging bytes (18432)
#define FLASH_SMEM (2 * KVB + PB)                // 55296 bytes

__device__ __forceinline__ void flash_ld_kv16(const __half* __restrict__ Kg,
                                              const __half* __restrict__ Vg,
                                              uint32_t kbuf_u, int tid) {
#pragma unroll
    for (int i = 0; i < 2; ++i) {               // K: 64 rows x 8 chunks
        int t = i * 256 + tid;
        int r = t >> 3, c = t & 7;
        cp_async16(kbuf_u + (r * LDH + c * 8) * 2, Kg + (size_t)r * D_ + c * 8);
    }
#pragma unroll
    for (int i = 0; i < 2; ++i) {               // V
        int t = i * 256 + tid;
        int r = t >> 3, c = t & 7;
        cp_async16(kbuf_u + KT_ * LDH * 2 + (r * LDH + c * 8) * 2,
                   Vg + (size_t)r * D_ + c * 8);
    }
}

__global__ __launch_bounds__(256, 2) void flash_kernel()
{
    extern __shared__ __half fsh16[];
    const uint32_t fsh_u = smem_u32(fsh16);
    const uint32_t Ps_u = fsh_u + 2 * KVB;      // Q staging region
    __half* Ps = fsh16 + 2 * (KVB / 2);

    const int tid = threadIdx.x, lane = tid & 31, warp = tid >> 5;
    const int g = lane >> 2, tg = lane & 3;
    const int qt = (gridDim.x - 1) - blockIdx.x;       // heavy blocks first
    const int h  = blockIdx.y;
    const int b  = blockIdx.z;
    const size_t base = (size_t)b * S_ * D_ + h * HD_;
    const int m0 = warp * 16;

    // ldmatrix lane geometry
    const int aRowL = m0 + (lane & 7) + ((lane >> 3) & 1) * 8;
    const int aKL   = ((lane >> 4) & 1) * 8;
    const int bRowL = (lane & 7) + ((lane >> 4) & 1) * 8;
    const int bKL   = ((lane >> 3) & 1) * 8;
    const int vRowL = (lane & 7) + ((lane >> 3) & 1) * 8;
    const int vColL = ((lane >> 4) & 1) * 8;

    // ---- Stage Q via smem once, hoist fragments to registers ----
    uint32_t aq[4][4];
    {
        const uint4* Qg = (const uint4*)(g_Q16 + base + (size_t)qt * QT_ * D_);
        for (int t = tid; t < QT_ * 8; t += 256) {
            int r = t >> 3, c = t & 7;
            *(uint4*)(Ps + r * LDH + c * 8) = Qg[(size_t)r * (D_ / 8) + c];
        }
        __syncthreads();
#pragma unroll
        for (int ki = 0; ki < 4; ++ki)
            ldsm4(aq[ki][0], aq[ki][1], aq[ki][2], aq[ki][3],
                  Ps_u + (aRowL * LDH + ki * 16 + aKL) * 2);
    }

    float m0r = -1e30f, m1r = -1e30f, l0 = 0.f, l1 = 0.f;
    float d_o[8][4];
#pragma unroll
    for (int ni = 0; ni < 8; ++ni)
#pragma unroll
        for (int r = 0; r < 4; ++r) d_o[ni][r] = 0.f;

    const int njt = 2 * qt + 2;

    flash_ld_kv16(g_K16 + base, g_V16 + base, fsh_u, tid);
    CP_COMMIT();

    for (int jt = 0; jt < njt; ++jt) {
        CP_WAIT(0);
        __syncthreads();
        if (jt + 1 < njt) {
            flash_ld_kv16(g_K16 + base + (size_t)(jt + 1) * KT_ * D_,
                          g_V16 + base + (size_t)(jt + 1) * KT_ * D_,
                          fsh_u + ((jt + 1) & 1) * KVB, tid);
            CP_COMMIT();
        }

        // Warps 0-3 (rows 0-63 of the Q tile) have ALL columns masked on the
        // second diagonal tile (cols start at 128qt+64 > their max row):
        // the whole update is a bit-exact no-op, so skip the compute.
        if (jt == 2 * qt + 1 && warp < 4) continue;

        const uint32_t Ks_u = fsh_u + (jt & 1) * KVB;
        const uint32_t Vs_u = Ks_u + KT_ * LDH * 2;

        // ---- S = Q @ K^T ----
        float ds[8][4];
#pragma unroll
        for (int ni = 0; ni < 8; ++ni)
#pragma unroll
            for (int r = 0; r < 4; ++r) ds[ni][r] = 0.f;

#pragma unroll
        for (int ki = 0; ki < 4; ++ki) {
            const int kk = ki * 16;
            uint32_t bf[8][2];
#pragma unroll
            for (int p = 0; p < 4; ++p)
                ldsm4(bf[2 * p][0], bf[2 * p][1], bf[2 * p + 1][0], bf[2 * p + 1][1],
                      Ks_u + ((bRowL + p * 16) * LDH + kk + bKL) * 2);
#pragma unroll
            for (int ni = 0; ni < 8; ++ni)
                mma16(ds[ni], aq[ki], bf[ni]);
        }

        // ---- causal mask (diagonal-region KV tiles only) ----
        if (jt >= 2 * qt) {
            const int grow0 = qt * QT_ + m0 + g;
            const int grow1 = grow0 + 8;
#pragma unroll
            for (int ni = 0; ni < 8; ++ni) {
                const int c0 = jt * KT_ + ni * 8 + 2 * tg;
                if (c0     > grow0) ds[ni][0] = -1e30f;
                if (c0 + 1 > grow0) ds[ni][1] = -1e30f;
                if (c0     > grow1) ds[ni][2] = -1e30f;
                if (c0 + 1 > grow1) ds[ni][3] = -1e30f;
            }
        }

        // ---- online softmax (rows fully in-warp) ----
        float rm0 = -1e30f, rm1 = -1e30f;
#pragma unroll
        for (int ni = 0; ni < 8; ++ni) {
            rm0 = fmaxf(rm0, fmaxf(ds[ni][0], ds[ni][1]));
            rm1 = fmaxf(rm1, fmaxf(ds[ni][2], ds[ni][3]));
        }
        rm0 = fmaxf(rm0, __shfl_xor_sync(0xffffffffu, rm0, 1));
        rm0 = fmaxf(rm0, __shfl_xor_sync(0xffffffffu, rm0, 2));
        rm1 = fmaxf(rm1, __shfl_xor_sync(0xffffffffu, rm1, 1));
        rm1 = fmaxf(rm1, __shfl_xor_sync(0xffffffffu, rm1, 2));

        const float mn0 = fmaxf(m0r, rm0);
        const float mn1 = fmaxf(m1r, rm1);
        const float a0 = __expf(m0r - mn0);
        const float a1 = __expf(m1r - mn1);
        m0r = mn0; m1r = mn1;

        // ---- exp + pack P directly into A-fragment registers ----
        uint32_t pp[8][2];
        float rs0 = 0.f, rs1 = 0.f;
#pragma unroll
        for (int ni = 0; ni < 8; ++ni) {
            float p00 = __expf(ds[ni][0] - mn0);
            float p01 = __expf(ds[ni][1] - mn0);
            float p10 = __expf(ds[ni][2] - mn1);
            float p11 = __expf(ds[ni][3] - mn1);
            rs0 += p00 + p01;
            rs1 += p10 + p11;
            pp[ni][0] = pack_h2(p00, p01);   // rows g   (vals 0,1)
            pp[ni][1] = pack_h2(p10, p11);   // rows g+8 (vals 2,3)
        }
        rs0 += __shfl_xor_sync(0xffffffffu, rs0, 1);
        rs0 += __shfl_xor_sync(0xffffffffu, rs0, 2);
        rs1 += __shfl_xor_sync(0xffffffffu, rs1, 1);
        rs1 += __shfl_xor_sync(0xffffffffu, rs1, 2);
        l0 = l0 * a0 + rs0;
        l1 = l1 * a1 + rs1;

#pragma unroll
        for (int ni = 0; ni < 8; ++ni) {
            d_o[ni][0] *= a0; d_o[ni][1] *= a0;
            d_o[ni][2] *= a1; d_o[ni][3] *= a1;
        }

        // ---- O += P @ V  (A-frag = pp registers; B = V^T via ldmatrix.trans)
#pragma unroll
        for (int ki = 0; ki < 4; ++ki) {
            const int kk = ki * 16;
            uint32_t ap[4] = { pp[2 * ki][0], pp[2 * ki][1],
                               pp[2 * ki + 1][0], pp[2 * ki + 1][1] };
            uint32_t bv[8][2];
#pragma unroll
            for (int p = 0; p < 4; ++p)
                ldsm4t(bv[2 * p][0], bv[2 * p][1], bv[2 * p + 1][0], bv[2 * p + 1][1],
                       Vs_u + ((kk + vRowL) * LDH + p * 16 + vColL) * 2);
#pragma unroll
            for (int ni = 0; ni < 8; ++ni)
                mma16(d_o[ni], ap, bv[ni]);
        }
    }

    // ---- normalize + store fp16 (input to out_gemm) ----
    const float inv0 = 1.0f / l0;
    const float inv1 = 1.0f / l1;
    __half* Og = g_O16 + base + (size_t)qt * QT_ * D_;
    const int row0 = m0 + g;
#pragma unroll
    for (int ni = 0; ni < 8; ++ni) {
        const int col = ni * 8 + 2 * tg;
        *(__half2*)(Og + (size_t)row0 * D_ + col) =
            __floats2half2_rn(d_o[ni][0] * inv0, d_o[ni][1] * inv0);
        *(__half2*)(Og + (size_t)(row0 + 8) * D_ + col) =
            __floats2half2_rn(d_o[ni][2] * inv1, d_o[ni][3] * inv1);
    }
}

// ---------------------------------------------------------------------------
extern "C" void kernel_launch(void* const* d_in, const int* in_sizes, int n_in,
                              void* d_out, int out_size)
{
    const float* q  = (const float*)d_in[0];
    const float* k  = (const float*)d_in[1];
    const float* v  = (const float*)d_in[2];
    // d_in[3]: mask — fixed causal tril, handled analytically in flash_kernel
    const float* Wq = (const float*)d_in[4];
    const float* bq = (const float*)d_in[5];
    const float* Wk = (const float*)d_in[6];
    const float* bk = (const float*)d_in[7];
    const float* Wv = (const float*)d_in[8];
    const float* bv = (const float*)d_in[9];
    const float* Wo = (const float*)d_in[10];
    const float* bo = (const float*)d_in[11];
    float* out = (float*)d_out;

    static bool s_configured = false;
    if (!s_configured) {
        cudaFuncSetAttribute(flash_kernel,
                             cudaFuncAttributeMaxDynamicSharedMemorySize, FLASH_SMEM);
        cudaFuncSetAttribute(qkv_gemm_kernel,
                             cudaFuncAttributeMaxDynamicSharedMemorySize, GSMEM);
        cudaFuncSetAttribute(out_gemm_kernel,
                             cudaFuncAttributeMaxDynamicSharedMemorySize, GSMEM);
        s_configured = true;
    }

    cvt_kernel<<<dim3(256, 7), 256>>>(q, k, v, Wq, Wk, Wv, Wo);
    qkv_gemm_kernel<<<dim3(D_ / 128, NTOK / 128, 3), 256, GSMEM>>>(bq, bk, bv);
    flash_kernel<<<dim3(S_ / QT_, H_, B_), 256, FLASH_SMEM>>>();
    out_gemm_kernel<<<dim3(D_ / 128, NTOK / 128, 1), 256, GSMEM>>>(bo, out);
}